// round 4
// baseline (speedup 1.0000x reference)
#include <cuda_runtime.h>
#include <cstdint>
#include <math.h>

// Problem dims
#define BB   4
#define LL   1024
#define DD   1024
#define NHH  16
#define DHH  64
#define HH   2730
#define HP   2816          // padded hidden (22*128, 88*32)
#define MM   (BB*LL)       // 4096 rows

// ---------------- scratch (device globals: allocation-free rule) ----------------
__device__ __align__(256) float g_xn  [MM*DD];
__device__ __align__(256) float g_qkv [MM*3*DD];
__device__ __align__(256) float g_attn[MM*DD];
__device__ __align__(256) float g_x2  [MM*DD];
__device__ __align__(256) float g_xn2 [MM*DD];
__device__ __align__(256) float g_h1  [MM*HP];
__device__ __align__(256) float g_h2  [MM*HP];
__device__ __align__(256) float g_g   [MM*HP];
__device__ __align__(256) float g_wxT [3*DD*DD];
__device__ __align__(256) float g_woT [DD*DD];
__device__ __align__(256) float g_uT  [HP*DD];
__device__ __align__(256) float g_vT  [HP*DD];
__device__ __align__(256) float g_wT  [DD*HP];

// ---------------- helpers ----------------
__device__ __forceinline__ uint32_t smem_to_u32(const void* p) {
    uint32_t a;
    asm("{ .reg .u64 t; cvta.to.shared.u64 t, %1; cvt.u32.u64 %0, t; }" : "=r"(a) : "l"(p));
    return a;
}
__device__ __forceinline__ float to_tf32(float x) {
    uint32_t o, i = __float_as_uint(x);
    asm("cvt.rna.tf32.f32 %0, %1;" : "=r"(o) : "r"(i));
    return __uint_as_float(o);
}
__device__ __forceinline__ void cp_async16(uint32_t saddr, const void* g) {
    asm volatile("cp.async.cg.shared.global [%0], [%1], 16;" :: "r"(saddr), "l"(g) : "memory");
}
__device__ __forceinline__ void mma_m16n8k8(float* c, const uint32_t* a, const uint32_t* b) {
    asm volatile(
        "mma.sync.aligned.m16n8k8.row.col.f32.tf32.tf32.f32 "
        "{%0,%1,%2,%3}, {%4,%5,%6,%7}, {%8,%9}, {%0,%1,%2,%3};"
        : "+f"(c[0]), "+f"(c[1]), "+f"(c[2]), "+f"(c[3])
        : "r"(a[0]), "r"(a[1]), "r"(a[2]), "r"(a[3]), "r"(b[0]), "r"(b[1]));
}

// ---------------- transpose + tf32 round (weights) ----------------
__global__ void transpose_round_kernel(const float* __restrict__ in, float* __restrict__ out,
                                       int Rin, int Cin, int Crows, int RowLen) {
    __shared__ float t[32][33];
    int r0 = blockIdx.x * 32;
    int c0 = blockIdx.y * 32;
    for (int i = threadIdx.y; i < 32; i += 8) {
        int r = r0 + i, c = c0 + threadIdx.x;
        t[i][threadIdx.x] = (r < Rin && c < Cin) ? in[(size_t)r * Cin + c] : 0.f;
    }
    __syncthreads();
    for (int i = threadIdx.y; i < 32; i += 8) {
        int c = c0 + i, r = r0 + threadIdx.x;
        if (c < Crows && r < RowLen)
            out[(size_t)c * RowLen + r] = to_tf32(t[threadIdx.x][i]);
    }
}

// ---------------- RMSNorm (tf32-rounded output) ----------------
__global__ void rmsnorm_kernel(const float* __restrict__ x,
                               const float* __restrict__ w,
                               float* __restrict__ y) {
    int row = blockIdx.x;
    const float* xr = x + (size_t)row * DD;
    float* yr = y + (size_t)row * DD;
    float s = 0.f;
    for (int i = threadIdx.x; i < DD; i += blockDim.x) { float v = xr[i]; s += v * v; }
    __shared__ float red[32];
    #pragma unroll
    for (int o = 16; o; o >>= 1) s += __shfl_xor_sync(0xffffffffu, s, o);
    int warp = threadIdx.x >> 5, lane = threadIdx.x & 31;
    if (lane == 0) red[warp] = s;
    __syncthreads();
    if (warp == 0) {
        s = (lane < (int)(blockDim.x >> 5)) ? red[lane] : 0.f;
        #pragma unroll
        for (int o = 16; o; o >>= 1) s += __shfl_xor_sync(0xffffffffu, s, o);
        if (lane == 0) red[0] = s;
    }
    __syncthreads();
    float rrms = rsqrtf(red[0] / (float)DD + 1e-8f);
    for (int i = threadIdx.x; i < DD; i += blockDim.x) yr[i] = to_tf32(w[i] * xr[i] * rrms);
}

// ---------------- tf32 mma.sync GEMM: C[M,N] = A[M,K] @ Bt[N,K]^T (+bias)(+res) ----------------
// CTA tile 256x128, BK=32, 8 warps (4m x 2n), warp tile 64x64, 4-stage cp.async.
// smem per stage: A 256x36 + B 128x36 floats (padded; conflict-free frag loads).
#define STAGE_BYTES  55296u     // (256+128)*36*4
#define STAGE_FLOATS 13824
__global__ void __launch_bounds__(256)
gemm_tc_kernel(const float* __restrict__ A, const float* __restrict__ Bt,
               float* __restrict__ C, int M, int N, int K,
               const float* __restrict__ bias, const float* __restrict__ res) {
    extern __shared__ float sm[];
    const uint32_t smem_u32 = smem_to_u32(sm);
    const int tid = threadIdx.x;
    const int lane = tid & 31, wid = tid >> 5;
    const int warp_m = wid & 3, warp_n = wid >> 2;
    const int row0 = blockIdx.y * 256, col0 = blockIdx.x * 128;
    const int KT = K >> 5;

    // global load mapping
    const float* agp = A  + (size_t)(row0 + tid) * K;          // 8 x float4 / thread
    const int lr = tid >> 1, half = tid & 1;
    const float* bgp = Bt + (size_t)(col0 + lr) * K + half * 16; // 4 x float4 / thread
    const uint32_t a_s = (uint32_t)tid * 144u;
    const uint32_t b_s = 36864u + (uint32_t)lr * 144u + (uint32_t)half * 64u;

    #define LOAD_STAGE(s, kt) do { \
        uint32_t _base = smem_u32 + (uint32_t)(s) * STAGE_BYTES; \
        const float* _a = agp + (kt) * 32; \
        const float* _b = bgp + (kt) * 32; \
        _Pragma("unroll") \
        for (int _i = 0; _i < 8; _i++) cp_async16(_base + a_s + _i * 16u, _a + _i * 4); \
        _Pragma("unroll") \
        for (int _i = 0; _i < 4; _i++) cp_async16(_base + b_s + _i * 16u, _b + _i * 4); \
        asm volatile("cp.async.commit_group;" ::: "memory"); \
    } while (0)

    LOAD_STAGE(0, 0);
    LOAD_STAGE(1, 1);
    LOAD_STAGE(2, 2);

    float acc[4][8][4];
    #pragma unroll
    for (int i = 0; i < 4; i++)
        #pragma unroll
        for (int j = 0; j < 8; j++)
            #pragma unroll
            for (int k = 0; k < 4; k++) acc[i][j][k] = 0.f;

    const int g = lane >> 2, t = lane & 3;

    for (int kt = 0; kt < KT; kt++) {
        const int s = kt & 3;
        if (kt + 2 < KT)      asm volatile("cp.async.wait_group 2;" ::: "memory");
        else if (kt + 1 < KT) asm volatile("cp.async.wait_group 1;" ::: "memory");
        else                  asm volatile("cp.async.wait_group 0;" ::: "memory");
        __syncthreads();
        if (kt + 3 < KT) LOAD_STAGE((kt + 3) & 3, kt + 3);

        const float* as = sm + s * STAGE_FLOATS;
        const float* bs = as + 9216;
        #pragma unroll
        for (int kk = 0; kk < 4; kk++) {
            const int k0 = kk * 8 + t;
            uint32_t af[4][4], bf[8][2];
            #pragma unroll
            for (int mt = 0; mt < 4; mt++) {
                int r = warp_m * 64 + mt * 16 + g;
                af[mt][0] = __float_as_uint(as[r * 36 + k0]);
                af[mt][1] = __float_as_uint(as[(r + 8) * 36 + k0]);
                af[mt][2] = __float_as_uint(as[r * 36 + k0 + 4]);
                af[mt][3] = __float_as_uint(as[(r + 8) * 36 + k0 + 4]);
            }
            #pragma unroll
            for (int nt = 0; nt < 8; nt++) {
                int n = warp_n * 64 + nt * 8 + g;
                bf[nt][0] = __float_as_uint(bs[n * 36 + k0]);
                bf[nt][1] = __float_as_uint(bs[n * 36 + k0 + 4]);
            }
            #pragma unroll
            for (int mt = 0; mt < 4; mt++)
                #pragma unroll
                for (int nt = 0; nt < 8; nt++)
                    mma_m16n8k8(acc[mt][nt], af[mt], bf[nt]);
        }
    }

    #pragma unroll
    for (int mt = 0; mt < 4; mt++) {
        int r = row0 + warp_m * 64 + mt * 16 + g;
        #pragma unroll
        for (int nt = 0; nt < 8; nt++) {
            int cc = col0 + warp_n * 64 + nt * 8 + 2 * t;
            float b0 = 0.f, b1 = 0.f;
            if (bias) { b0 = bias[cc]; b1 = bias[cc + 1]; }
            float v0 = acc[mt][nt][0] + b0;
            float v1 = acc[mt][nt][1] + b1;
            float v2 = acc[mt][nt][2] + b0;
            float v3 = acc[mt][nt][3] + b1;
            if (res) {
                const float* r0p = res + (size_t)r * N + cc;
                const float* r1p = res + (size_t)(r + 8) * N + cc;
                v0 += r0p[0]; v1 += r0p[1];
                v2 += r1p[0]; v3 += r1p[1];
            }
            float2 o0 = {v0, v1}, o1 = {v2, v3};
            *(float2*)&C[(size_t)r * N + cc] = o0;
            *(float2*)&C[(size_t)(r + 8) * N + cc] = o1;
        }
    }
    #undef LOAD_STAGE
}

// ---------------- Flash attention (causal, fp32, 32-key chunked softmax) ----------------
__global__ void __launch_bounds__(256, 2)
flash_attn_kernel(const float* __restrict__ qkv, float* __restrict__ out) {
    int qt = blockIdx.x;
    int bh = blockIdx.y;
    int b = bh >> 4, h = bh & 15;
    __shared__ float Ks[64][72];
    __shared__ float Vs[64][72];
    int tid = threadIdx.x;
    int qr  = tid >> 2;
    int sub = tid & 3;
    int qg  = qt * 64 + qr;
    const size_t base = (size_t)b * LL * (3 * DD);
    const float scale = 0.03125f;   // D^-0.5

    float q[16];
    {
        const float* qp = qkv + base + (size_t)qg * (3 * DD) + h * 64 + sub * 16;
        #pragma unroll
        for (int i = 0; i < 16; i++) q[i] = qp[i];
    }
    float acc[16];
    #pragma unroll
    for (int i = 0; i < 16; i++) acc[i] = 0.f;
    float mrow = -INFINITY, lrow = 0.f;

    for (int kt = 0; kt <= qt; kt++) {
        __syncthreads();
        for (int i = tid; i < 64 * 64; i += 256) {
            int r = i >> 6, d = i & 63;
            size_t src = base + (size_t)(kt * 64 + r) * (3 * DD) + h * 64 + d;
            Ks[r][d] = qkv[src + DD];
            Vs[r][d] = qkv[src + 2 * DD];
        }
        __syncthreads();
        bool diag = (kt == qt);

        #pragma unroll
        for (int half = 0; half < 2; half++) {
            if (diag && half == 1 && qr < 32) break;   // warp-uniform
            float sv[32];
            #pragma unroll
            for (int j = 0; j < 32; j++) {
                int jj = half * 32 + j;
                const float4* kp = (const float4*)&Ks[jj][sub * 16];
                float4 k0 = kp[0], k1 = kp[1], k2 = kp[2], k3 = kp[3];
                float s = q[0]*k0.x + q[1]*k0.y + q[2]*k0.z + q[3]*k0.w
                        + q[4]*k1.x + q[5]*k1.y + q[6]*k1.z + q[7]*k1.w
                        + q[8]*k2.x + q[9]*k2.y + q[10]*k2.z + q[11]*k2.w
                        + q[12]*k3.x + q[13]*k3.y + q[14]*k3.z + q[15]*k3.w;
                s += __shfl_xor_sync(0xffffffffu, s, 1);
                s += __shfl_xor_sync(0xffffffffu, s, 2);
                sv[j] = s * scale;
                if (diag && jj > qr) sv[j] = -1e30f;
            }
            float mt_ = -1e30f;
            #pragma unroll
            for (int j = 0; j < 32; j++) mt_ = fmaxf(mt_, sv[j]);
            float mnew = fmaxf(mrow, mt_);
            float corr = __expf(mrow - mnew);
            lrow *= corr;
            #pragma unroll
            for (int d = 0; d < 16; d++) acc[d] *= corr;
            #pragma unroll
            for (int j = 0; j < 32; j++) {
                int jj = half * 32 + j;
                float p = __expf(sv[j] - mnew);
                lrow += p;
                const float4* vp = (const float4*)&Vs[jj][sub * 16];
                float4 v0 = vp[0], v1 = vp[1], v2 = vp[2], v3 = vp[3];
                acc[0]  += p * v0.x;  acc[1]  += p * v0.y;  acc[2]  += p * v0.z;  acc[3]  += p * v0.w;
                acc[4]  += p * v1.x;  acc[5]  += p * v1.y;  acc[6]  += p * v1.z;  acc[7]  += p * v1.w;
                acc[8]  += p * v2.x;  acc[9]  += p * v2.y;  acc[10] += p * v2.z;  acc[11] += p * v2.w;
                acc[12] += p * v3.x;  acc[13] += p * v3.y;  acc[14] += p * v3.z;  acc[15] += p * v3.w;
            }
            mrow = mnew;
        }
    }
    float inv = 1.f / lrow;
    float* op = out + ((size_t)(b * LL + qg)) * DD + h * 64 + sub * 16;
    #pragma unroll
    for (int i = 0; i < 16; i++) op[i] = to_tf32(acc[i] * inv);
}

// ---------------- SwiGLU gate: g = tf32(silu(h1) * h2) ----------------
__global__ void silu_mul_kernel(const float* __restrict__ a,
                                const float* __restrict__ b,
                                float* __restrict__ g, int n) {
    int i = blockIdx.x * blockDim.x + threadIdx.x;
    if (i < n) {
        float x = a[i];
        g[i] = to_tf32((x / (1.f + expf(-x))) * b[i]);
    }
}

// ---------------- launch ----------------
extern "C" void kernel_launch(void* const* d_in, const int* in_sizes, int n_in,
                              void* d_out, int out_size) {
    const float* x         = (const float*)d_in[0];
    const float* wx        = (const float*)d_in[2];
    const float* bx        = (const float*)d_in[3];
    const float* wo        = (const float*)d_in[4];
    const float* bo        = (const float*)d_in[5];
    const float* mhanorm_w = (const float*)d_in[6];
    const float* ffnorm_w  = (const float*)d_in[7];
    const float* u         = (const float*)d_in[8];
    const float* v         = (const float*)d_in[9];
    const float* w         = (const float*)d_in[10];
    float* out = (float*)d_out;

    float *xn, *qkv, *attn, *x2, *xn2, *h1, *h2, *gg, *wxT, *woT, *uT, *vT, *wT;
    cudaGetSymbolAddress((void**)&xn,   g_xn);
    cudaGetSymbolAddress((void**)&qkv,  g_qkv);
    cudaGetSymbolAddress((void**)&attn, g_attn);
    cudaGetSymbolAddress((void**)&x2,   g_x2);
    cudaGetSymbolAddress((void**)&xn2,  g_xn2);
    cudaGetSymbolAddress((void**)&h1,   g_h1);
    cudaGetSymbolAddress((void**)&h2,   g_h2);
    cudaGetSymbolAddress((void**)&gg,   g_g);
    cudaGetSymbolAddress((void**)&wxT,  g_wxT);
    cudaGetSymbolAddress((void**)&woT,  g_woT);
    cudaGetSymbolAddress((void**)&uT,   g_uT);
    cudaGetSymbolAddress((void**)&vT,   g_vT);
    cudaGetSymbolAddress((void**)&wT,   g_wT);

    const int GSMEM = 4 * 55296;   // 221184 B
    cudaFuncSetAttribute(gemm_tc_kernel,
                         cudaFuncAttributeMaxDynamicSharedMemorySize, GSMEM);
    dim3 tb(32, 8);

    // Ordered so the ncu capture window (~launch 2-5) hits the big GEMM / attention.
    transpose_round_kernel<<<dim3(32, 96), tb>>>(wx, wxT, DD, 3 * DD, 3 * DD, DD);   // 0
    rmsnorm_kernel<<<MM, 256>>>(x, mhanorm_w, xn);                                    // 1
    gemm_tc_kernel<<<dim3(24, 16), 256, GSMEM>>>(xn, wxT, qkv, MM, 3 * DD, DD, bx, nullptr); // 2
    flash_attn_kernel<<<dim3(LL / 64, BB * NHH), 256>>>(qkv, attn);                   // 3
    transpose_round_kernel<<<dim3(32, 32), tb>>>(wo, woT, DD, DD, DD, DD);            // 4
    gemm_tc_kernel<<<dim3(8, 16), 256, GSMEM>>>(attn, woT, x2, MM, DD, DD, bo, x);    // 5
    rmsnorm_kernel<<<MM, 256>>>(x2, ffnorm_w, xn2);                                   // 6
    transpose_round_kernel<<<dim3(32, 88), tb>>>(u,  uT,  DD, HH, HP, DD);            // 7
    transpose_round_kernel<<<dim3(32, 88), tb>>>(v,  vT,  DD, HH, HP, DD);            // 8
    gemm_tc_kernel<<<dim3(22, 16), 256, GSMEM>>>(xn2, uT, h1, MM, HP, DD, nullptr, nullptr); // 9
    gemm_tc_kernel<<<dim3(22, 16), 256, GSMEM>>>(xn2, vT, h2, MM, HP, DD, nullptr, nullptr); // 10
    transpose_round_kernel<<<dim3(88, 32), tb>>>(w,  wT,  HH, DD, DD, HP);            // 11
    int n = MM * HP;
    silu_mul_kernel<<<(n + 255) / 256, 256>>>(h1, h2, gg, n);                         // 12
    gemm_tc_kernel<<<dim3(8, 16), 256, GSMEM>>>(gg, wT, out, MM, DD, HP, nullptr, x2); // 13
}

// round 5
// speedup vs baseline: 1.1955x; 1.1955x over previous
#include <cuda_runtime.h>
#include <cstdint>
#include <math.h>

// Problem dims
#define BB   4
#define LL   1024
#define DD   1024
#define NHH  16
#define DHH  64
#define HH   2730
#define HP   2816          // padded hidden (22*128, 88*32)
#define MM   (BB*LL)       // 4096 rows

// ---------------- scratch (device globals: allocation-free rule) ----------------
__device__ __align__(256) float g_xn  [MM*DD];
__device__ __align__(256) float g_qkv [MM*3*DD];
__device__ __align__(256) float g_attn[MM*DD];
__device__ __align__(256) float g_x2  [MM*DD];
__device__ __align__(256) float g_xn2 [MM*DD];
__device__ __align__(256) float g_h1  [MM*HP];
__device__ __align__(256) float g_h2  [MM*HP];
__device__ __align__(256) float g_g   [MM*HP];
__device__ __align__(256) float g_wxT [3*DD*DD];
__device__ __align__(256) float g_woT [DD*DD];
__device__ __align__(256) float g_uT  [HP*DD];
__device__ __align__(256) float g_vT  [HP*DD];
__device__ __align__(256) float g_wT  [DD*HP];

// ---------------- helpers ----------------
__device__ __forceinline__ uint32_t smem_to_u32(const void* p) {
    uint32_t a;
    asm("{ .reg .u64 t; cvta.to.shared.u64 t, %1; cvt.u32.u64 %0, t; }" : "=r"(a) : "l"(p));
    return a;
}
__device__ __forceinline__ float to_tf32(float x) {
    uint32_t o, i = __float_as_uint(x);
    asm("cvt.rna.tf32.f32 %0, %1;" : "=r"(o) : "r"(i));
    return __uint_as_float(o);
}
__device__ __forceinline__ void cp_async16(uint32_t saddr, const void* g) {
    asm volatile("cp.async.cg.shared.global [%0], [%1], 16;" :: "r"(saddr), "l"(g) : "memory");
}
__device__ __forceinline__ void mma_m16n8k8(float* c, const uint32_t* a, const uint32_t* b) {
    asm volatile(
        "mma.sync.aligned.m16n8k8.row.col.f32.tf32.tf32.f32 "
        "{%0,%1,%2,%3}, {%4,%5,%6,%7}, {%8,%9}, {%0,%1,%2,%3};"
        : "+f"(c[0]), "+f"(c[1]), "+f"(c[2]), "+f"(c[3])
        : "r"(a[0]), "r"(a[1]), "r"(a[2]), "r"(a[3]), "r"(b[0]), "r"(b[1]));
}

// ---------------- transpose + tf32 round (weights) ----------------
__global__ void transpose_round_kernel(const float* __restrict__ in, float* __restrict__ out,
                                       int Rin, int Cin, int Crows, int RowLen) {
    __shared__ float t[32][33];
    int r0 = blockIdx.x * 32;
    int c0 = blockIdx.y * 32;
    for (int i = threadIdx.y; i < 32; i += 8) {
        int r = r0 + i, c = c0 + threadIdx.x;
        t[i][threadIdx.x] = (r < Rin && c < Cin) ? in[(size_t)r * Cin + c] : 0.f;
    }
    __syncthreads();
    for (int i = threadIdx.y; i < 32; i += 8) {
        int c = c0 + i, r = r0 + threadIdx.x;
        if (c < Crows && r < RowLen)
            out[(size_t)c * RowLen + r] = to_tf32(t[threadIdx.x][i]);
    }
}

// ---------------- RMSNorm (tf32-rounded output) ----------------
__global__ void rmsnorm_kernel(const float* __restrict__ x,
                               const float* __restrict__ w,
                               float* __restrict__ y) {
    int row = blockIdx.x;
    const float* xr = x + (size_t)row * DD;
    float* yr = y + (size_t)row * DD;
    float s = 0.f;
    for (int i = threadIdx.x; i < DD; i += blockDim.x) { float v = xr[i]; s += v * v; }
    __shared__ float red[32];
    #pragma unroll
    for (int o = 16; o; o >>= 1) s += __shfl_xor_sync(0xffffffffu, s, o);
    int warp = threadIdx.x >> 5, lane = threadIdx.x & 31;
    if (lane == 0) red[warp] = s;
    __syncthreads();
    if (warp == 0) {
        s = (lane < (int)(blockDim.x >> 5)) ? red[lane] : 0.f;
        #pragma unroll
        for (int o = 16; o; o >>= 1) s += __shfl_xor_sync(0xffffffffu, s, o);
        if (lane == 0) red[0] = s;
    }
    __syncthreads();
    float rrms = rsqrtf(red[0] / (float)DD + 1e-8f);
    for (int i = threadIdx.x; i < DD; i += blockDim.x) yr[i] = to_tf32(w[i] * xr[i] * rrms);
}

// ---------------- tf32 mma.sync GEMM: C[M,N] = A[M,K] @ Bt[N,K]^T (+bias)(+res) ----------------
// CTA tile 128x128, BK=32, 8 warps (2m x 4n), warp tile 64x32, 3-stage cp.async.
// smem per stage: A 128x36 + B 128x36 floats (padded). 2 CTAs/SM.
__global__ void __launch_bounds__(256, 2)
gemm_tc_kernel(const float* __restrict__ A, const float* __restrict__ Bt,
               float* __restrict__ C, int M, int N, int K,
               const float* __restrict__ bias, const float* __restrict__ res) {
    extern __shared__ float sm[];
    const uint32_t smem_u32 = smem_to_u32(sm);
    const int tid = threadIdx.x;
    const int lane = tid & 31, wid = tid >> 5;
    const int warp_m = wid & 1, warp_n = wid >> 1;
    const int row0 = blockIdx.y * 128, col0 = blockIdx.x * 128;
    const int KT = K >> 5;

    // global load mapping: 256 threads, each 4x float4 per operand tile
    const int lr = tid >> 3;            // 0..31
    const float* ag = A  + (size_t)(row0 + lr) * K + (tid & 7) * 4;
    const float* bg = Bt + (size_t)(col0 + lr) * K + (tid & 7) * 4;
    const uint32_t s_off = smem_u32 + (uint32_t)lr * 144u + (uint32_t)(tid & 7) * 16u;

    #define LOAD_STAGE(s, kt) do { \
        uint32_t _b = s_off + (uint32_t)(s) * 36864u; \
        const float* _a = ag + (kt) * 32; \
        const float* _bp = bg + (kt) * 32; \
        _Pragma("unroll") \
        for (int _i = 0; _i < 4; _i++) { \
            cp_async16(_b + _i * 4608u,          _a  + (size_t)_i * 32 * K); \
            cp_async16(_b + 18432u + _i * 4608u, _bp + (size_t)_i * 32 * K); \
        } \
        asm volatile("cp.async.commit_group;" ::: "memory"); \
    } while (0)

    LOAD_STAGE(0, 0);
    LOAD_STAGE(1, 1);

    float acc[4][4][4];
    #pragma unroll
    for (int i = 0; i < 4; i++)
        #pragma unroll
        for (int j = 0; j < 4; j++)
            #pragma unroll
            for (int k = 0; k < 4; k++) acc[i][j][k] = 0.f;

    const int g = lane >> 2, t = lane & 3;

    for (int kt = 0; kt < KT; kt++) {
        const int s = kt % 3;
        asm volatile("cp.async.wait_group 1;" ::: "memory");
        __syncthreads();
        if (kt + 2 < KT) LOAD_STAGE((kt + 2) % 3, kt + 2);

        const float* as = sm + s * 9216;
        const float* bs = as + 4608;
        #pragma unroll
        for (int kk = 0; kk < 4; kk++) {
            const int k0 = kk * 8 + t;
            uint32_t af[4][4], bf[4][2];
            #pragma unroll
            for (int mt = 0; mt < 4; mt++) {
                int r = warp_m * 64 + mt * 16 + g;
                af[mt][0] = __float_as_uint(as[r * 36 + k0]);
                af[mt][1] = __float_as_uint(as[(r + 8) * 36 + k0]);
                af[mt][2] = __float_as_uint(as[r * 36 + k0 + 4]);
                af[mt][3] = __float_as_uint(as[(r + 8) * 36 + k0 + 4]);
            }
            #pragma unroll
            for (int nt = 0; nt < 4; nt++) {
                int n = warp_n * 32 + nt * 8 + g;
                bf[nt][0] = __float_as_uint(bs[n * 36 + k0]);
                bf[nt][1] = __float_as_uint(bs[n * 36 + k0 + 4]);
            }
            #pragma unroll
            for (int mt = 0; mt < 4; mt++)
                #pragma unroll
                for (int nt = 0; nt < 4; nt++)
                    mma_m16n8k8(acc[mt][nt], af[mt], bf[nt]);
        }
    }

    asm volatile("cp.async.wait_group 0;" ::: "memory");

    #pragma unroll
    for (int mt = 0; mt < 4; mt++) {
        int r = row0 + warp_m * 64 + mt * 16 + g;
        #pragma unroll
        for (int nt = 0; nt < 4; nt++) {
            int cc = col0 + warp_n * 32 + nt * 8 + 2 * t;
            float b0 = 0.f, b1 = 0.f;
            if (bias) { b0 = bias[cc]; b1 = bias[cc + 1]; }
            float v0 = acc[mt][nt][0] + b0;
            float v1 = acc[mt][nt][1] + b1;
            float v2 = acc[mt][nt][2] + b0;
            float v3 = acc[mt][nt][3] + b1;
            if (res) {
                const float* r0p = res + (size_t)r * N + cc;
                const float* r1p = res + (size_t)(r + 8) * N + cc;
                v0 += r0p[0]; v1 += r0p[1];
                v2 += r1p[0]; v3 += r1p[1];
            }
            float2 o0 = {v0, v1}, o1 = {v2, v3};
            *(float2*)&C[(size_t)r * N + cc] = o0;
            *(float2*)&C[(size_t)(r + 8) * N + cc] = o1;
        }
    }
    #undef LOAD_STAGE
}

// ---------------- Flash attention (causal, fp32, 32-key chunked softmax) ----------------
__global__ void __launch_bounds__(256, 2)
flash_attn_kernel(const float* __restrict__ qkv, float* __restrict__ out) {
    int qt = blockIdx.x;
    int bh = blockIdx.y;
    int b = bh >> 4, h = bh & 15;
    __shared__ float Ks[64][72];
    __shared__ float Vs[64][72];
    int tid = threadIdx.x;
    int qr  = tid >> 2;
    int sub = tid & 3;
    int qg  = qt * 64 + qr;
    const size_t base = (size_t)b * LL * (3 * DD);
    const float scale = 0.03125f;   // D^-0.5

    float q[16];
    {
        const float* qp = qkv + base + (size_t)qg * (3 * DD) + h * 64 + sub * 16;
        #pragma unroll
        for (int i = 0; i < 16; i++) q[i] = qp[i];
    }
    float acc[16];
    #pragma unroll
    for (int i = 0; i < 16; i++) acc[i] = 0.f;
    float mrow = -INFINITY, lrow = 0.f;

    for (int kt = 0; kt <= qt; kt++) {
        __syncthreads();
        for (int i = tid; i < 64 * 64; i += 256) {
            int r = i >> 6, d = i & 63;
            size_t src = base + (size_t)(kt * 64 + r) * (3 * DD) + h * 64 + d;
            Ks[r][d] = qkv[src + DD];
            Vs[r][d] = qkv[src + 2 * DD];
        }
        __syncthreads();
        bool diag = (kt == qt);

        #pragma unroll
        for (int half = 0; half < 2; half++) {
            if (diag && half == 1 && qr < 32) break;   // warp-uniform
            float sv[32];
            #pragma unroll
            for (int j = 0; j < 32; j++) {
                int jj = half * 32 + j;
                const float4* kp = (const float4*)&Ks[jj][sub * 16];
                float4 k0 = kp[0], k1 = kp[1], k2 = kp[2], k3 = kp[3];
                float s = q[0]*k0.x + q[1]*k0.y + q[2]*k0.z + q[3]*k0.w
                        + q[4]*k1.x + q[5]*k1.y + q[6]*k1.z + q[7]*k1.w
                        + q[8]*k2.x + q[9]*k2.y + q[10]*k2.z + q[11]*k2.w
                        + q[12]*k3.x + q[13]*k3.y + q[14]*k3.z + q[15]*k3.w;
                s += __shfl_xor_sync(0xffffffffu, s, 1);
                s += __shfl_xor_sync(0xffffffffu, s, 2);
                sv[j] = s * scale;
                if (diag && jj > qr) sv[j] = -1e30f;
            }
            float mt_ = -1e30f;
            #pragma unroll
            for (int j = 0; j < 32; j++) mt_ = fmaxf(mt_, sv[j]);
            float mnew = fmaxf(mrow, mt_);
            float corr = __expf(mrow - mnew);
            lrow *= corr;
            #pragma unroll
            for (int d = 0; d < 16; d++) acc[d] *= corr;
            #pragma unroll
            for (int j = 0; j < 32; j++) {
                int jj = half * 32 + j;
                float p = __expf(sv[j] - mnew);
                lrow += p;
                const float4* vp = (const float4*)&Vs[jj][sub * 16];
                float4 v0 = vp[0], v1 = vp[1], v2 = vp[2], v3 = vp[3];
                acc[0]  += p * v0.x;  acc[1]  += p * v0.y;  acc[2]  += p * v0.z;  acc[3]  += p * v0.w;
                acc[4]  += p * v1.x;  acc[5]  += p * v1.y;  acc[6]  += p * v1.z;  acc[7]  += p * v1.w;
                acc[8]  += p * v2.x;  acc[9]  += p * v2.y;  acc[10] += p * v2.z;  acc[11] += p * v2.w;
                acc[12] += p * v3.x;  acc[13] += p * v3.y;  acc[14] += p * v3.z;  acc[15] += p * v3.w;
            }
            mrow = mnew;
        }
    }
    float inv = 1.f / lrow;
    float* op = out + ((size_t)(b * LL + qg)) * DD + h * 64 + sub * 16;
    #pragma unroll
    for (int i = 0; i < 16; i++) op[i] = to_tf32(acc[i] * inv);
}

// ---------------- SwiGLU gate: g = tf32(silu(h1) * h2) ----------------
__global__ void silu_mul_kernel(const float* __restrict__ a,
                                const float* __restrict__ b,
                                float* __restrict__ g, int n) {
    int i = blockIdx.x * blockDim.x + threadIdx.x;
    if (i < n) {
        float x = a[i];
        g[i] = to_tf32((x / (1.f + expf(-x))) * b[i]);
    }
}

// ---------------- launch ----------------
extern "C" void kernel_launch(void* const* d_in, const int* in_sizes, int n_in,
                              void* d_out, int out_size) {
    const float* x         = (const float*)d_in[0];
    const float* wx        = (const float*)d_in[2];
    const float* bx        = (const float*)d_in[3];
    const float* wo        = (const float*)d_in[4];
    const float* bo        = (const float*)d_in[5];
    const float* mhanorm_w = (const float*)d_in[6];
    const float* ffnorm_w  = (const float*)d_in[7];
    const float* u         = (const float*)d_in[8];
    const float* v         = (const float*)d_in[9];
    const float* w         = (const float*)d_in[10];
    float* out = (float*)d_out;

    float *xn, *qkv, *attn, *x2, *xn2, *h1, *h2, *gg, *wxT, *woT, *uT, *vT, *wT;
    cudaGetSymbolAddress((void**)&xn,   g_xn);
    cudaGetSymbolAddress((void**)&qkv,  g_qkv);
    cudaGetSymbolAddress((void**)&attn, g_attn);
    cudaGetSymbolAddress((void**)&x2,   g_x2);
    cudaGetSymbolAddress((void**)&xn2,  g_xn2);
    cudaGetSymbolAddress((void**)&h1,   g_h1);
    cudaGetSymbolAddress((void**)&h2,   g_h2);
    cudaGetSymbolAddress((void**)&gg,   g_g);
    cudaGetSymbolAddress((void**)&wxT,  g_wxT);
    cudaGetSymbolAddress((void**)&woT,  g_woT);
    cudaGetSymbolAddress((void**)&uT,   g_uT);
    cudaGetSymbolAddress((void**)&vT,   g_vT);
    cudaGetSymbolAddress((void**)&wT,   g_wT);

    const int GSMEM = 3 * 36864;   // 110592 B; 2 CTAs/SM
    cudaFuncSetAttribute(gemm_tc_kernel,
                         cudaFuncAttributeMaxDynamicSharedMemorySize, GSMEM);
    dim3 tb(32, 8);

    // Ordered so the ncu capture window (skip 5) lands on a GEMM.
    transpose_round_kernel<<<dim3(32, 96), tb>>>(wx, wxT, DD, 3 * DD, 3 * DD, DD);   // 0
    rmsnorm_kernel<<<MM, 256>>>(x, mhanorm_w, xn);                                    // 1
    gemm_tc_kernel<<<dim3(24, 32), 256, GSMEM>>>(xn, wxT, qkv, MM, 3 * DD, DD, bx, nullptr); // 2
    flash_attn_kernel<<<dim3(LL / 64, BB * NHH), 256>>>(qkv, attn);                   // 3
    transpose_round_kernel<<<dim3(32, 32), tb>>>(wo, woT, DD, DD, DD, DD);            // 4
    gemm_tc_kernel<<<dim3(8, 32), 256, GSMEM>>>(attn, woT, x2, MM, DD, DD, bo, x);    // 5
    rmsnorm_kernel<<<MM, 256>>>(x2, ffnorm_w, xn2);                                   // 6
    transpose_round_kernel<<<dim3(32, 88), tb>>>(u,  uT,  DD, HH, HP, DD);            // 7
    transpose_round_kernel<<<dim3(32, 88), tb>>>(v,  vT,  DD, HH, HP, DD);            // 8
    gemm_tc_kernel<<<dim3(22, 32), 256, GSMEM>>>(xn2, uT, h1, MM, HP, DD, nullptr, nullptr); // 9
    gemm_tc_kernel<<<dim3(22, 32), 256, GSMEM>>>(xn2, vT, h2, MM, HP, DD, nullptr, nullptr); // 10
    transpose_round_kernel<<<dim3(88, 32), tb>>>(w,  wT,  HH, DD, DD, HP);            // 11
    int n = MM * HP;
    silu_mul_kernel<<<(n + 255) / 256, 256>>>(h1, h2, gg, n);                         // 12
    gemm_tc_kernel<<<dim3(8, 32), 256, GSMEM>>>(gg, wT, out, MM, DD, HP, nullptr, x2); // 13
}

// round 6
// speedup vs baseline: 2.4868x; 2.0802x over previous
#include <cuda_runtime.h>
#include <cstdint>
#include <math.h>

// Problem dims
#define BB   4
#define LL   1024
#define DD   1024
#define NHH  16
#define DHH  64
#define HH   2730
#define HP   2816          // padded hidden (22*128, 88*32)
#define MM   (BB*LL)       // 4096 rows

// ---------------- scratch (device globals: allocation-free rule) ----------------
__device__ __align__(256) float g_xn  [MM*DD];
__device__ __align__(256) float g_qkv [MM*3*DD];
__device__ __align__(256) float g_attn[MM*DD];
__device__ __align__(256) float g_x2  [MM*DD];
__device__ __align__(256) float g_xn2 [MM*DD];
__device__ __align__(256) float g_h1  [MM*HP];
__device__ __align__(256) float g_h2  [MM*HP];
__device__ __align__(256) float g_g   [MM*HP];
__device__ __align__(256) float g_wxT [3*DD*DD];
__device__ __align__(256) float g_woT [DD*DD];
__device__ __align__(256) float g_uT  [HP*DD];
__device__ __align__(256) float g_vT  [HP*DD];
__device__ __align__(256) float g_wT  [DD*HP];

// ---------------- helpers ----------------
__device__ __forceinline__ uint32_t smem_to_u32(const void* p) {
    uint32_t a;
    asm("{ .reg .u64 t; cvta.to.shared.u64 t, %1; cvt.u32.u64 %0, t; }" : "=r"(a) : "l"(p));
    return a;
}
__device__ __forceinline__ float to_tf32(float x) {
    uint32_t o, i = __float_as_uint(x);
    asm("cvt.rna.tf32.f32 %0, %1;" : "=r"(o) : "r"(i));
    return __uint_as_float(o);
}
__device__ __forceinline__ void cp_async16(uint32_t saddr, const void* g) {
    asm volatile("cp.async.cg.shared.global [%0], [%1], 16;" :: "r"(saddr), "l"(g) : "memory");
}
__device__ __forceinline__ void mma_m16n8k8(float* c, const uint32_t* a, const uint32_t* b) {
    asm volatile(
        "mma.sync.aligned.m16n8k8.row.col.f32.tf32.tf32.f32 "
        "{%0,%1,%2,%3}, {%4,%5,%6,%7}, {%8,%9}, {%0,%1,%2,%3};"
        : "+f"(c[0]), "+f"(c[1]), "+f"(c[2]), "+f"(c[3])
        : "r"(a[0]), "r"(a[1]), "r"(a[2]), "r"(a[3]), "r"(b[0]), "r"(b[1]));
}

// ---------------- transpose + tf32 round (weights) ----------------
__global__ void transpose_round_kernel(const float* __restrict__ in, float* __restrict__ out,
                                       int Rin, int Cin, int Crows, int RowLen) {
    __shared__ float t[32][33];
    int r0 = blockIdx.x * 32;
    int c0 = blockIdx.y * 32;
    for (int i = threadIdx.y; i < 32; i += 8) {
        int r = r0 + i, c = c0 + threadIdx.x;
        t[i][threadIdx.x] = (r < Rin && c < Cin) ? in[(size_t)r * Cin + c] : 0.f;
    }
    __syncthreads();
    for (int i = threadIdx.y; i < 32; i += 8) {
        int c = c0 + i, r = r0 + threadIdx.x;
        if (c < Crows && r < RowLen)
            out[(size_t)c * RowLen + r] = to_tf32(t[threadIdx.x][i]);
    }
}

// ---------------- RMSNorm (tf32-rounded output) ----------------
__global__ void rmsnorm_kernel(const float* __restrict__ x,
                               const float* __restrict__ w,
                               float* __restrict__ y) {
    int row = blockIdx.x;
    const float* xr = x + (size_t)row * DD;
    float* yr = y + (size_t)row * DD;
    float s = 0.f;
    for (int i = threadIdx.x; i < DD; i += blockDim.x) { float v = xr[i]; s += v * v; }
    __shared__ float red[32];
    #pragma unroll
    for (int o = 16; o; o >>= 1) s += __shfl_xor_sync(0xffffffffu, s, o);
    int warp = threadIdx.x >> 5, lane = threadIdx.x & 31;
    if (lane == 0) red[warp] = s;
    __syncthreads();
    if (warp == 0) {
        s = (lane < (int)(blockDim.x >> 5)) ? red[lane] : 0.f;
        #pragma unroll
        for (int o = 16; o; o >>= 1) s += __shfl_xor_sync(0xffffffffu, s, o);
        if (lane == 0) red[0] = s;
    }
    __syncthreads();
    float rrms = rsqrtf(red[0] / (float)DD + 1e-8f);
    for (int i = threadIdx.x; i < DD; i += blockDim.x) yr[i] = to_tf32(w[i] * xr[i] * rrms);
}

// ---------------- tf32 mma.sync GEMM: C[M,N] = A[M,K] @ Bt[N,K]^T (+bias)(+res) ----------------
__global__ void __launch_bounds__(256, 2)
gemm_tc_kernel(const float* __restrict__ A, const float* __restrict__ Bt,
               float* __restrict__ C, int M, int N, int K,
               const float* __restrict__ bias, const float* __restrict__ res) {
    extern __shared__ float sm[];
    const uint32_t smem_u32 = smem_to_u32(sm);
    const int tid = threadIdx.x;
    const int lane = tid & 31, wid = tid >> 5;
    const int warp_m = wid & 1, warp_n = wid >> 1;
    const int row0 = blockIdx.y * 128, col0 = blockIdx.x * 128;
    const int KT = K >> 5;

    const int lr = tid >> 3;            // 0..31
    const float* ag = A  + (size_t)(row0 + lr) * K + (tid & 7) * 4;
    const float* bg = Bt + (size_t)(col0 + lr) * K + (tid & 7) * 4;
    const uint32_t s_off = smem_u32 + (uint32_t)lr * 144u + (uint32_t)(tid & 7) * 16u;

    #define LOAD_STAGE(s, kt) do { \
        uint32_t _b = s_off + (uint32_t)(s) * 36864u; \
        const float* _a = ag + (kt) * 32; \
        const float* _bp = bg + (kt) * 32; \
        _Pragma("unroll") \
        for (int _i = 0; _i < 4; _i++) { \
            cp_async16(_b + _i * 4608u,          _a  + (size_t)_i * 32 * K); \
            cp_async16(_b + 18432u + _i * 4608u, _bp + (size_t)_i * 32 * K); \
        } \
        asm volatile("cp.async.commit_group;" ::: "memory"); \
    } while (0)

    LOAD_STAGE(0, 0);
    LOAD_STAGE(1, 1);

    float acc[4][4][4];
    #pragma unroll
    for (int i = 0; i < 4; i++)
        #pragma unroll
        for (int j = 0; j < 4; j++)
            #pragma unroll
            for (int k = 0; k < 4; k++) acc[i][j][k] = 0.f;

    const int g = lane >> 2, t = lane & 3;

    for (int kt = 0; kt < KT; kt++) {
        const int s = kt % 3;
        asm volatile("cp.async.wait_group 1;" ::: "memory");
        __syncthreads();
        if (kt + 2 < KT) LOAD_STAGE((kt + 2) % 3, kt + 2);

        const float* as = sm + s * 9216;
        const float* bs = as + 4608;
        #pragma unroll
        for (int kk = 0; kk < 4; kk++) {
            const int k0 = kk * 8 + t;
            uint32_t af[4][4], bf[4][2];
            #pragma unroll
            for (int mt = 0; mt < 4; mt++) {
                int r = warp_m * 64 + mt * 16 + g;
                af[mt][0] = __float_as_uint(as[r * 36 + k0]);
                af[mt][1] = __float_as_uint(as[(r + 8) * 36 + k0]);
                af[mt][2] = __float_as_uint(as[r * 36 + k0 + 4]);
                af[mt][3] = __float_as_uint(as[(r + 8) * 36 + k0 + 4]);
            }
            #pragma unroll
            for (int nt = 0; nt < 4; nt++) {
                int n = warp_n * 32 + nt * 8 + g;
                bf[nt][0] = __float_as_uint(bs[n * 36 + k0]);
                bf[nt][1] = __float_as_uint(bs[n * 36 + k0 + 4]);
            }
            #pragma unroll
            for (int mt = 0; mt < 4; mt++)
                #pragma unroll
                for (int nt = 0; nt < 4; nt++)
                    mma_m16n8k8(acc[mt][nt], af[mt], bf[nt]);
        }
    }

    asm volatile("cp.async.wait_group 0;" ::: "memory");

    #pragma unroll
    for (int mt = 0; mt < 4; mt++) {
        int r = row0 + warp_m * 64 + mt * 16 + g;
        #pragma unroll
        for (int nt = 0; nt < 4; nt++) {
            int cc = col0 + warp_n * 32 + nt * 8 + 2 * t;
            float b0 = 0.f, b1 = 0.f;
            if (bias) { b0 = bias[cc]; b1 = bias[cc + 1]; }
            float v0 = acc[mt][nt][0] + b0;
            float v1 = acc[mt][nt][1] + b1;
            float v2 = acc[mt][nt][2] + b0;
            float v3 = acc[mt][nt][3] + b1;
            if (res) {
                const float* r0p = res + (size_t)r * N + cc;
                const float* r1p = res + (size_t)(r + 8) * N + cc;
                v0 += r0p[0]; v1 += r0p[1];
                v2 += r1p[0]; v3 += r1p[1];
            }
            float2 o0 = {v0, v1}, o1 = {v2, v3};
            *(float2*)&C[(size_t)r * N + cc] = o0;
            *(float2*)&C[(size_t)(r + 8) * N + cc] = o1;
        }
    }
    #undef LOAD_STAGE
}

// ---------------- Tensor-core flash attention (causal, tf32 mma) ----------------
// CTA: 128 q-rows of one (b,h). 8 warps x 16 q-rows. Key tiles of 64.
// smem floats: KS[64*76] | VT[64*76] | QS[128*68] | PS[128*68]
#define ATT_KS   0
#define ATT_VT   4864
#define ATT_QS   9728
#define ATT_PS   18432
#define ATT_SMEMF 27136          // 108544 bytes
__global__ void __launch_bounds__(256, 2)
flash_attn_tc_kernel(const float* __restrict__ qkv, float* __restrict__ out) {
    extern __shared__ float fs[];
    float* KS = fs + ATT_KS;
    float* VT = fs + ATT_VT;
    float* QS = fs + ATT_QS;
    float* PS = fs + ATT_PS;

    const int qt = 7 - blockIdx.x;              // heavy tiles first
    const int bh = blockIdx.y;
    const int b = bh >> 4, h = bh & 15;
    const int tid = threadIdx.x;
    const int lane = tid & 31, w = tid >> 5;
    const int g = lane >> 2, t = lane & 3;
    const size_t base = (size_t)b * LL * (3 * DD);
    const float scale = 0.03125f;               // D^-0.5

    // stage Q (tf32-rounded, pre-scaled)
    for (int i = tid; i < 128 * 64; i += 256) {
        int r = i >> 6, d = i & 63;
        QS[r * 68 + d] = to_tf32(qkv[base + (size_t)(qt * 128 + r) * (3 * DD) + h * 64 + d]) * scale;
    }

    float oacc[8][4];
    #pragma unroll
    for (int i = 0; i < 8; i++)
        #pragma unroll
        for (int j = 0; j < 4; j++) oacc[i][j] = 0.f;
    float m0 = -INFINITY, m1 = -INFINITY, l0 = 0.f, l1 = 0.f;

    const int qrow0 = qt * 128 + w * 16;
    const int ktmax = 2 * qt + 1;
    const int ktlast_w = (qrow0 + 15) >> 6;     // last key tile this warp needs

    float* Pw = PS + (size_t)(w * 16) * 68;

    for (int kt = 0; kt <= ktmax; kt++) {
        __syncthreads();
        for (int i = tid; i < 64 * 64; i += 256) {
            int r = i >> 6, d = i & 63;
            size_t src = base + (size_t)(kt * 64 + r) * (3 * DD) + h * 64 + d;
            KS[r * 76 + d] = to_tf32(qkv[src + DD]);
            VT[d * 76 + r] = to_tf32(qkv[src + 2 * DD]);
        }
        __syncthreads();
        if (kt > ktlast_w) continue;

        // ---- S = Q @ K^T ----
        float sv[8][4];
        #pragma unroll
        for (int i = 0; i < 8; i++)
            #pragma unroll
            for (int j = 0; j < 4; j++) sv[i][j] = 0.f;
        #pragma unroll
        for (int kk = 0; kk < 8; kk++) {
            uint32_t qf[4];
            const int ro = (w * 16 + g) * 68 + kk * 8 + t;
            qf[0] = __float_as_uint(QS[ro]);
            qf[1] = __float_as_uint(QS[ro + 8 * 68]);
            qf[2] = __float_as_uint(QS[ro + 4]);
            qf[3] = __float_as_uint(QS[ro + 8 * 68 + 4]);
            #pragma unroll
            for (int nt = 0; nt < 8; nt++) {
                const int nb = (nt * 8 + g) * 76 + kk * 8 + t;
                uint32_t bf[2] = { __float_as_uint(KS[nb]), __float_as_uint(KS[nb + 4]) };
                mma_m16n8k8(sv[nt], qf, bf);
            }
        }

        // ---- causal mask ----
        if (kt * 64 + 63 > qrow0) {
            const int r0 = qrow0 + g, r1 = r0 + 8;
            #pragma unroll
            for (int nt = 0; nt < 8; nt++) {
                int kc = kt * 64 + nt * 8 + 2 * t;
                if (kc     > r0) sv[nt][0] = -1e30f;
                if (kc + 1 > r0) sv[nt][1] = -1e30f;
                if (kc     > r1) sv[nt][2] = -1e30f;
                if (kc + 1 > r1) sv[nt][3] = -1e30f;
            }
        }

        // ---- online softmax ----
        float m0t = -1e30f, m1t = -1e30f;
        #pragma unroll
        for (int nt = 0; nt < 8; nt++) {
            m0t = fmaxf(m0t, fmaxf(sv[nt][0], sv[nt][1]));
            m1t = fmaxf(m1t, fmaxf(sv[nt][2], sv[nt][3]));
        }
        m0t = fmaxf(m0t, __shfl_xor_sync(0xffffffffu, m0t, 1));
        m0t = fmaxf(m0t, __shfl_xor_sync(0xffffffffu, m0t, 2));
        m1t = fmaxf(m1t, __shfl_xor_sync(0xffffffffu, m1t, 1));
        m1t = fmaxf(m1t, __shfl_xor_sync(0xffffffffu, m1t, 2));
        float mn0 = fmaxf(m0, m0t), mn1 = fmaxf(m1, m1t);
        float c0 = __expf(m0 - mn0), c1 = __expf(m1 - mn1);
        float s0 = 0.f, s1 = 0.f;
        #pragma unroll
        for (int nt = 0; nt < 8; nt++) {
            sv[nt][0] = __expf(sv[nt][0] - mn0);
            sv[nt][1] = __expf(sv[nt][1] - mn0);
            sv[nt][2] = __expf(sv[nt][2] - mn1);
            sv[nt][3] = __expf(sv[nt][3] - mn1);
            s0 += sv[nt][0] + sv[nt][1];
            s1 += sv[nt][2] + sv[nt][3];
        }
        s0 += __shfl_xor_sync(0xffffffffu, s0, 1);
        s0 += __shfl_xor_sync(0xffffffffu, s0, 2);
        s1 += __shfl_xor_sync(0xffffffffu, s1, 1);
        s1 += __shfl_xor_sync(0xffffffffu, s1, 2);
        l0 = l0 * c0 + s0;
        l1 = l1 * c1 + s1;
        m0 = mn0; m1 = mn1;
        #pragma unroll
        for (int nt = 0; nt < 8; nt++) {
            oacc[nt][0] *= c0; oacc[nt][1] *= c0;
            oacc[nt][2] *= c1; oacc[nt][3] *= c1;
        }

        // ---- P to per-warp smem (tf32-rounded) ----
        #pragma unroll
        for (int nt = 0; nt < 8; nt++) {
            float2 p0 = { to_tf32(sv[nt][0]), to_tf32(sv[nt][1]) };
            float2 p1 = { to_tf32(sv[nt][2]), to_tf32(sv[nt][3]) };
            *(float2*)&Pw[g * 68 + nt * 8 + 2 * t]       = p0;
            *(float2*)&Pw[(g + 8) * 68 + nt * 8 + 2 * t] = p1;
        }
        __syncwarp();

        // ---- O += P @ V ----
        #pragma unroll
        for (int kk = 0; kk < 8; kk++) {
            uint32_t pf[4];
            const int po = g * 68 + kk * 8 + t;
            pf[0] = __float_as_uint(Pw[po]);
            pf[1] = __float_as_uint(Pw[po + 8 * 68]);
            pf[2] = __float_as_uint(Pw[po + 4]);
            pf[3] = __float_as_uint(Pw[po + 8 * 68 + 4]);
            #pragma unroll
            for (int nt = 0; nt < 8; nt++) {
                const int vb = (nt * 8 + g) * 76 + kk * 8 + t;
                uint32_t bf[2] = { __float_as_uint(VT[vb]), __float_as_uint(VT[vb + 4]) };
                mma_m16n8k8(oacc[nt], pf, bf);
            }
        }
    }

    // ---- epilogue ----
    const float i0 = 1.f / l0, i1 = 1.f / l1;
    const int r0 = qrow0 + g, r1 = r0 + 8;
    #pragma unroll
    for (int nt = 0; nt < 8; nt++) {
        int col = h * 64 + nt * 8 + 2 * t;
        float2 o0 = { to_tf32(oacc[nt][0] * i0), to_tf32(oacc[nt][1] * i0) };
        float2 o1 = { to_tf32(oacc[nt][2] * i1), to_tf32(oacc[nt][3] * i1) };
        *(float2*)&out[(size_t)(b * LL + r0) * DD + col] = o0;
        *(float2*)&out[(size_t)(b * LL + r1) * DD + col] = o1;
    }
}

// ---------------- SwiGLU gate: g = tf32(silu(h1) * h2) ----------------
__global__ void silu_mul_kernel(const float* __restrict__ a,
                                const float* __restrict__ b,
                                float* __restrict__ g, int n) {
    int i = blockIdx.x * blockDim.x + threadIdx.x;
    if (i < n) {
        float x = a[i];
        g[i] = to_tf32((x / (1.f + expf(-x))) * b[i]);
    }
}

// ---------------- launch ----------------
extern "C" void kernel_launch(void* const* d_in, const int* in_sizes, int n_in,
                              void* d_out, int out_size) {
    const float* x         = (const float*)d_in[0];
    const float* wx        = (const float*)d_in[2];
    const float* bx        = (const float*)d_in[3];
    const float* wo        = (const float*)d_in[4];
    const float* bo        = (const float*)d_in[5];
    const float* mhanorm_w = (const float*)d_in[6];
    const float* ffnorm_w  = (const float*)d_in[7];
    const float* u         = (const float*)d_in[8];
    const float* v         = (const float*)d_in[9];
    const float* w         = (const float*)d_in[10];
    float* out = (float*)d_out;

    float *xn, *qkv, *attn, *x2, *xn2, *h1, *h2, *gg, *wxT, *woT, *uT, *vT, *wT;
    cudaGetSymbolAddress((void**)&xn,   g_xn);
    cudaGetSymbolAddress((void**)&qkv,  g_qkv);
    cudaGetSymbolAddress((void**)&attn, g_attn);
    cudaGetSymbolAddress((void**)&x2,   g_x2);
    cudaGetSymbolAddress((void**)&xn2,  g_xn2);
    cudaGetSymbolAddress((void**)&h1,   g_h1);
    cudaGetSymbolAddress((void**)&h2,   g_h2);
    cudaGetSymbolAddress((void**)&gg,   g_g);
    cudaGetSymbolAddress((void**)&wxT,  g_wxT);
    cudaGetSymbolAddress((void**)&woT,  g_woT);
    cudaGetSymbolAddress((void**)&uT,   g_uT);
    cudaGetSymbolAddress((void**)&vT,   g_vT);
    cudaGetSymbolAddress((void**)&wT,   g_wT);

    const int GSMEM = 3 * 36864;      // 110592 B; 2 CTAs/SM
    const int ASMEM = ATT_SMEMF * 4;  // 108544 B; 2 CTAs/SM
    cudaFuncSetAttribute(gemm_tc_kernel,
                         cudaFuncAttributeMaxDynamicSharedMemorySize, GSMEM);
    cudaFuncSetAttribute(flash_attn_tc_kernel,
                         cudaFuncAttributeMaxDynamicSharedMemorySize, ASMEM);
    dim3 tb(32, 8);

    transpose_round_kernel<<<dim3(32, 96), tb>>>(wx, wxT, DD, 3 * DD, 3 * DD, DD);   // 0
    rmsnorm_kernel<<<MM, 256>>>(x, mhanorm_w, xn);                                    // 1
    gemm_tc_kernel<<<dim3(24, 32), 256, GSMEM>>>(xn, wxT, qkv, MM, 3 * DD, DD, bx, nullptr); // 2
    flash_attn_tc_kernel<<<dim3(LL / 128, BB * NHH), 256, ASMEM>>>(qkv, attn);        // 3
    transpose_round_kernel<<<dim3(32, 32), tb>>>(wo, woT, DD, DD, DD, DD);            // 4
    gemm_tc_kernel<<<dim3(8, 32), 256, GSMEM>>>(attn, woT, x2, MM, DD, DD, bo, x);    // 5
    rmsnorm_kernel<<<MM, 256>>>(x2, ffnorm_w, xn2);                                   // 6
    transpose_round_kernel<<<dim3(32, 88), tb>>>(u,  uT,  DD, HH, HP, DD);            // 7
    transpose_round_kernel<<<dim3(32, 88), tb>>>(v,  vT,  DD, HH, HP, DD);            // 8
    gemm_tc_kernel<<<dim3(22, 32), 256, GSMEM>>>(xn2, uT, h1, MM, HP, DD, nullptr, nullptr); // 9
    gemm_tc_kernel<<<dim3(22, 32), 256, GSMEM>>>(xn2, vT, h2, MM, HP, DD, nullptr, nullptr); // 10
    transpose_round_kernel<<<dim3(88, 32), tb>>>(w,  wT,  HH, DD, DD, HP);            // 11
    int n = MM * HP;
    silu_mul_kernel<<<(n + 255) / 256, 256>>>(h1, h2, gg, n);                         // 12
    gemm_tc_kernel<<<dim3(8, 32), 256, GSMEM>>>(gg, wT, out, MM, DD, HP, nullptr, x2); // 13
}